// round 9
// baseline (speedup 1.0000x reference)
#include <cuda_runtime.h>
#include <cuda_bf16.h>
#include <cstdint>

#define DD 2048
#define BB 256
#define TT 64

// scratch (static device arrays — no allocations)
__device__ float          g_u [BB * DD];   // 2 MB: u = E@(W-I) + E + hb
__device__ __nv_bfloat16  g_Eh[BB * DD];   // 1 MB
__device__ __nv_bfloat16  g_Wh[DD * DD];   // 8 MB: bf16(W - I)

// ---------------------------------------------------------------------------
// Kernel 0: convert (proven). 1 thread = 2 float4 -> one uint4 store.
// ---------------------------------------------------------------------------
__global__ __launch_bounds__(256) void convert_kernel(
    const float* __restrict__ E, const float* __restrict__ W)
{
    const int NWP = DD * DD / 8;              // 524288 W pairs
    const int j = blockIdx.x * 256 + threadIdx.x;
    if (j < NWP) {
        float4 a = reinterpret_cast<const float4*>(W)[j * 2];
        float4 b = reinterpret_cast<const float4*>(W)[j * 2 + 1];
        const int fbase = j * 8;
        const int r = fbase >> 11;
        const int d = r - (fbase & (DD - 1));
        if (d >= 0 && d < 4)      reinterpret_cast<float*>(&a)[d]     -= 1.0f;
        else if (d >= 4 && d < 8) reinterpret_cast<float*>(&b)[d - 4] -= 1.0f;
        __nv_bfloat162 p0 = __floats2bfloat162_rn(a.x, a.y);
        __nv_bfloat162 p1 = __floats2bfloat162_rn(a.z, a.w);
        __nv_bfloat162 p2 = __floats2bfloat162_rn(b.x, b.y);
        __nv_bfloat162 p3 = __floats2bfloat162_rn(b.z, b.w);
        uint4 o;
        o.x = *reinterpret_cast<uint32_t*>(&p0);
        o.y = *reinterpret_cast<uint32_t*>(&p1);
        o.z = *reinterpret_cast<uint32_t*>(&p2);
        o.w = *reinterpret_cast<uint32_t*>(&p3);
        reinterpret_cast<uint4*>(g_Wh)[j] = o;
    } else {
        const int k = j - NWP;
        float4 a = reinterpret_cast<const float4*>(E)[k * 2];
        float4 b = reinterpret_cast<const float4*>(E)[k * 2 + 1];
        __nv_bfloat162 p0 = __floats2bfloat162_rn(a.x, a.y);
        __nv_bfloat162 p1 = __floats2bfloat162_rn(a.z, a.w);
        __nv_bfloat162 p2 = __floats2bfloat162_rn(b.x, b.y);
        __nv_bfloat162 p3 = __floats2bfloat162_rn(b.z, b.w);
        uint4 o;
        o.x = *reinterpret_cast<uint32_t*>(&p0);
        o.y = *reinterpret_cast<uint32_t*>(&p1);
        o.z = *reinterpret_cast<uint32_t*>(&p2);
        o.w = *reinterpret_cast<uint32_t*>(&p3);
        reinterpret_cast<uint4*>(g_Eh)[k] = o;
    }
}

// ---------------------------------------------------------------------------
// helpers
// ---------------------------------------------------------------------------
__device__ __forceinline__ void mma16816(float* d, const uint32_t* a,
                                         uint32_t b0, uint32_t b1)
{
    asm volatile(
        "mma.sync.aligned.m16n8k16.row.col.f32.bf16.bf16.f32 "
        "{%0,%1,%2,%3}, {%4,%5,%6,%7}, {%8,%9}, {%0,%1,%2,%3};\n"
        : "+f"(d[0]), "+f"(d[1]), "+f"(d[2]), "+f"(d[3])
        : "r"(a[0]), "r"(a[1]), "r"(a[2]), "r"(a[3]), "r"(b0), "r"(b1));
}
__device__ __forceinline__ void ldsm_x4(uint32_t* r, uint32_t addr)
{
    asm volatile("ldmatrix.sync.aligned.m8n8.x4.shared.b16 {%0,%1,%2,%3}, [%4];\n"
                 : "=r"(r[0]), "=r"(r[1]), "=r"(r[2]), "=r"(r[3]) : "r"(addr));
}
__device__ __forceinline__ void ldsm_x4_t(uint32_t* r, uint32_t addr)
{
    asm volatile("ldmatrix.sync.aligned.m8n8.x4.trans.shared.b16 {%0,%1,%2,%3}, [%4];\n"
                 : "=r"(r[0]), "=r"(r[1]), "=r"(r[2]), "=r"(r[3]) : "r"(addr));
}
__device__ __forceinline__ void cp16(uint32_t saddr, const void* gaddr)
{
    asm volatile("cp.async.cg.shared.global [%0], [%1], 16;\n"
                 :: "r"(saddr), "l"(gaddr) : "memory");
}

// ---------------------------------------------------------------------------
// Kernel A: tensor-core GEMM, BM=BN=128, BK=64, 256 threads (8 warps 2x4).
//   U = Eh @ Wh + E + hb.  Grid (16, 2) = 32 CTAs.
// L2 traffic: 32 CTAs x (A 512KB + B 512KB) = 32 MB (was 64 MB at 64x64).
// Warp tile 64x32. A tile: 128 rows x 128B (swizzled). B tile: two half-
// tiles [64 rows x 128B] (n-cols 0-63 / 64-127), same swizzle per half.
// ---------------------------------------------------------------------------
__global__ __launch_bounds__(256) void gemm_u_kernel(
    const float* __restrict__ E, const float* __restrict__ hb)
{
    extern __shared__ __align__(1024) char smem[];
    const uint32_t base = (uint32_t)__cvta_generic_to_shared(smem);
    // stage s (0/1):  A[s] = base + s*32768          (16 KB: 128 rows x 128B)
    //                 Bh[s][h] = base + s*32768 + 16384 + h*8192  (64 rows x 128B)

    const int tid  = threadIdx.x;
    const int lane = tid & 31;
    const int wid  = tid >> 5;
    const int wm   = (wid >> 2) << 6;   // 0 / 64
    const int wn   = (wid & 3) << 5;    // 0,32,64,96
    const int bm   = blockIdx.y << 7;
    const int bn   = blockIdx.x << 7;

    float acc[4][4][4];
    #pragma unroll
    for (int i = 0; i < 4; i++)
        #pragma unroll
        for (int j = 0; j < 4; j++)
            #pragma unroll
            for (int k = 0; k < 4; k++) acc[i][j][k] = 0.f;

    // cp.async mapping: 8 chunks/thread (A: 4, B: 4)
    const int r0 = tid >> 3;            // 0..31
    const int c0 = tid & 7;
    const uint32_t swz = (uint32_t)((c0 ^ (r0 & 7)) << 4);   // same for r0+32k
    // A chunk j (j=0..3): row r0+32j, smem off = ((r0+32j)<<7) + swz
    const __nv_bfloat16* gA = g_Eh + (size_t)(bm + r0) * DD + c0 * 8;
    // B chunk m (m=0..3): half h=m>>1, row r0+32*(m&1)
    const __nv_bfloat16* gB = g_Wh + (size_t)r0 * DD + bn + c0 * 8;

    // ldmatrix addressing
    const int l15 = lane & 15;
    const int l7  = lane & 7;
    const int kcB = lane >> 4;
    const int halfB   = wn >> 6;                  // 0 or 1
    const int nChunkB = (wn & 63) >> 3;           // 0,4 within half... (wn&63)>>3 in {0,4}
    // per-g (g=0,1): n0 = wn + 16g ; half = n0>>6 ; chunkBase = (n0&63)>>3

    #define LOAD_TILES(s, k0)                                                   \
        {                                                                       \
            const uint32_t sa = base + (uint32_t)((s) * 32768);                 \
            _Pragma("unroll")                                                   \
            for (int j = 0; j < 4; j++)                                         \
                cp16(sa + (uint32_t)((r0 + 32 * j) << 7) + swz,                 \
                     gA + (size_t)(32 * j) * DD + (k0));                        \
            _Pragma("unroll")                                                   \
            for (int m = 0; m < 4; m++) {                                       \
                const int h = m >> 1, rr = r0 + 32 * (m & 1);                   \
                cp16(sa + 16384u + (uint32_t)(h * 8192)                         \
                        + (uint32_t)(rr << 7) + swz,                            \
                     gB + (size_t)((k0) + rr - r0) * DD + h * 64);              \
            }                                                                   \
            asm volatile("cp.async.commit_group;\n" ::: "memory");              \
        }

    LOAD_TILES(0, 0);

    const int NIT = DD / 64;   // 32
    for (int it = 0; it < NIT; it++) {
        const int s = it & 1;
        if (it + 1 < NIT) {
            LOAD_TILES(s ^ 1, (it + 1) * 64);
            asm volatile("cp.async.wait_group 1;\n" ::: "memory");
        } else {
            asm volatile("cp.async.wait_group 0;\n" ::: "memory");
        }
        __syncthreads();

        const uint32_t sa = base + (uint32_t)(s * 32768);
        #pragma unroll
        for (int kk = 0; kk < 4; kk++) {
            const int kchunk = kk * 2 + kcB;
            uint32_t a[4][4], b[2][4];
            #pragma unroll
            for (int im = 0; im < 4; im++)
                ldsm_x4(a[im], sa + (uint32_t)((wm + im * 16 + l15) << 7)
                                  + (uint32_t)((kchunk ^ l7) << 4));
            const int krow = kk * 16 + l15;
            #pragma unroll
            for (int g = 0; g < 2; g++) {
                const int n0 = wn + 16 * g;
                const uint32_t sb = sa + 16384u + (uint32_t)((n0 >> 6) * 8192);
                const int cb = ((n0 & 63) >> 3) + kcB;
                ldsm_x4_t(b[g], sb + (uint32_t)(krow << 7)
                                   + (uint32_t)((cb ^ (krow & 7)) << 4));
            }
            #pragma unroll
            for (int im = 0; im < 4; im++) {
                mma16816(acc[im][0], a[im], b[0][0], b[0][1]);
                mma16816(acc[im][1], a[im], b[0][2], b[0][3]);
                mma16816(acc[im][2], a[im], b[1][0], b[1][1]);
                mma16816(acc[im][3], a[im], b[1][2], b[1][3]);
            }
        }
        __syncthreads();
    }
    #undef LOAD_TILES

    // epilogue: u = acc + E (exact identity) + hb
    // acc[im][j]: rows bm+wm+im*16+(lane>>2)(+8), cols bn+wn+j*8+(lane&3)*2(+1)
    #pragma unroll
    for (int im = 0; im < 4; im++) {
        const int row0e = bm + wm + im * 16 + (lane >> 2);
        #pragma unroll
        for (int j = 0; j < 4; j++) {
            const int col = bn + wn + j * 8 + ((lane & 3) << 1);
            const float h0 = hb[col], h1 = hb[col + 1];
            g_u[(size_t)row0e * DD + col]
                = acc[im][j][0] + E[(size_t)row0e * DD + col] + h0;
            g_u[(size_t)row0e * DD + col + 1]
                = acc[im][j][1] + E[(size_t)row0e * DD + col + 1] + h1;
            g_u[(size_t)(row0e + 8) * DD + col]
                = acc[im][j][2] + E[(size_t)(row0e + 8) * DD + col] + h0;
            g_u[(size_t)(row0e + 8) * DD + col + 1]
                = acc[im][j][3] + E[(size_t)(row0e + 8) * DD + col + 1] + h1;
        }
    }
}

// ---------------------------------------------------------------------------
// Kernel B: scoring (round-8 passing version, verbatim). Single wave:
// grid (256, 8) x 128 thr, 16 CTAs/SM.
// ---------------------------------------------------------------------------
__global__ __launch_bounds__(128, 16) void score_kernel(
    const float* __restrict__ E,
    const float* __restrict__ theo,
    const float* __restrict__ cand,
    const float* __restrict__ vb,
    float* __restrict__ out)
{
    const int b    = blockIdx.x;
    const int tc   = blockIdx.y;       // 0..7
    const int tid  = threadIdx.x;
    const int lane = tid & 31;
    const int wid  = tid >> 5;         // 0..3

    __shared__ float u_s[DD];
    __shared__ float red[8];
    __shared__ float s_vb, s_pos;

    float pv = 0.f, pp = 0.f;
    #pragma unroll
    for (int h = 0; h < 4; h++) {
        const int i = h * 512 + tid * 4;
        float4 u4 = *reinterpret_cast<const float4*>(&g_u[(size_t)b * DD + i]);
        *reinterpret_cast<float4*>(&u_s[i]) = u4;
        float4 e4 = *reinterpret_cast<const float4*>(&E[(size_t)b * DD + i]);
        float4 v4 = *reinterpret_cast<const float4*>(&vb[i]);
        pv += e4.x * v4.x + e4.y * v4.y + e4.z * v4.z + e4.w * v4.w;
        if (tc == 0) {
            float4 c4 = *reinterpret_cast<const float4*>(&cand[(size_t)b * DD + i]);
            pp += u4.x * c4.x + u4.y * c4.y + u4.z * c4.z + u4.w * c4.w;
        }
    }
    #pragma unroll
    for (int o = 16; o > 0; o >>= 1) {
        pv += __shfl_xor_sync(0xFFFFFFFFu, pv, o);
        pp += __shfl_xor_sync(0xFFFFFFFFu, pp, o);
    }
    if (lane == 0) { red[wid] = pv; red[4 + wid] = pp; }
    __syncthreads();
    if (tid == 0) {
        float v = red[0] + red[1] + red[2] + red[3];
        float p = red[4] + red[5] + red[6] + red[7];
        s_vb  = v;
        s_pos = p + v;
    }
    __syncthreads();
    const float vbb = s_vb;

    const int t0 = tc * 8 + wid * 2;
    const float4* ra  = reinterpret_cast<const float4*>(&theo[((size_t)b * TT + t0) * DD]);
    const float4* rb  = ra + DD / 4;
    const float4* u4p = reinterpret_cast<const float4*>(u_s);

    float s0 = 0.f, s1 = 0.f;
    #pragma unroll 4
    for (int i = lane; i < DD / 4; i += 32) {
        float4 x = __ldcs(&ra[i]);
        float4 y = __ldcs(&rb[i]);
        float4 u = u4p[i];
        s0 += x.x * u.x + x.y * u.y + x.z * u.z + x.w * u.w;
        s1 += y.x * u.x + y.y * u.y + y.z * u.z + y.w * u.w;
    }
    #pragma unroll
    for (int o = 16; o > 0; o >>= 1) {
        s0 += __shfl_xor_sync(0xFFFFFFFFu, s0, o);
        s1 += __shfl_xor_sync(0xFFFFFFFFu, s1, o);
    }
    if (lane == 0) {
        out[b * (TT + 1) + 1 + t0]     = s0 + vbb;
        out[b * (TT + 1) + 1 + t0 + 1] = s1 + vbb;
    }
    if (tc == 0 && tid == 0) out[b * (TT + 1)] = s_pos;
}

// ---------------------------------------------------------------------------
// launch: 0=experimental [B,D], 1=theoretical [B,T,D], 2=candidate [B,D],
//         3=W [D,D], 4=vb [D], 5=hb [D] ; out fp32 [B, 1+T]
// ---------------------------------------------------------------------------
extern "C" void kernel_launch(void* const* d_in, const int* in_sizes, int n_in,
                              void* d_out, int out_size)
{
    const float* E    = (const float*)d_in[0];
    const float* theo = (const float*)d_in[1];
    const float* cand = (const float*)d_in[2];
    const float* W    = (const float*)d_in[3];
    const float* vb   = (const float*)d_in[4];
    const float* hb   = (const float*)d_in[5];
    float*       out  = (float*)d_out;

    const int SMEM = 2 * 32768;   // 64 KB dynamic
    cudaFuncSetAttribute(gemm_u_kernel,
                         cudaFuncAttributeMaxDynamicSharedMemorySize, SMEM);

    const int npairs = DD * DD / 8 + BB * DD / 8;   // 589824
    convert_kernel<<<npairs / 256, 256>>>(E, W);
    gemm_u_kernel<<<dim3(DD / 128, BB / 128), 256, SMEM>>>(E, hb);
    score_kernel<<<dim3(BB, 8), 128>>>(E, theo, cand, vb, out);
}

// round 10
// speedup vs baseline: 1.4985x; 1.4985x over previous
#include <cuda_runtime.h>
#include <cuda_bf16.h>
#include <cstdint>

#define DD 2048
#define BB 256
#define TT 64

// scratch (static device arrays — no allocations)
__device__ float          g_u [BB * DD];   // 2 MB: u = E@(W-I) + E + hb
__device__ __nv_bfloat16  g_Eh[BB * DD];   // 1 MB
__device__ __nv_bfloat16  g_Wh[DD * DD];   // 8 MB: bf16(W - I)

// ---------------------------------------------------------------------------
// Kernel 0: convert (proven). 1 thread = 2 float4 -> one uint4 store.
// ---------------------------------------------------------------------------
__global__ __launch_bounds__(256) void convert_kernel(
    const float* __restrict__ E, const float* __restrict__ W)
{
    const int NWP = DD * DD / 8;              // 524288 W pairs
    const int j = blockIdx.x * 256 + threadIdx.x;
    if (j < NWP) {
        float4 a = reinterpret_cast<const float4*>(W)[j * 2];
        float4 b = reinterpret_cast<const float4*>(W)[j * 2 + 1];
        const int fbase = j * 8;
        const int r = fbase >> 11;
        const int d = r - (fbase & (DD - 1));
        if (d >= 0 && d < 4)      reinterpret_cast<float*>(&a)[d]     -= 1.0f;
        else if (d >= 4 && d < 8) reinterpret_cast<float*>(&b)[d - 4] -= 1.0f;
        __nv_bfloat162 p0 = __floats2bfloat162_rn(a.x, a.y);
        __nv_bfloat162 p1 = __floats2bfloat162_rn(a.z, a.w);
        __nv_bfloat162 p2 = __floats2bfloat162_rn(b.x, b.y);
        __nv_bfloat162 p3 = __floats2bfloat162_rn(b.z, b.w);
        uint4 o;
        o.x = *reinterpret_cast<uint32_t*>(&p0);
        o.y = *reinterpret_cast<uint32_t*>(&p1);
        o.z = *reinterpret_cast<uint32_t*>(&p2);
        o.w = *reinterpret_cast<uint32_t*>(&p3);
        reinterpret_cast<uint4*>(g_Wh)[j] = o;
    } else {
        const int k = j - NWP;
        float4 a = reinterpret_cast<const float4*>(E)[k * 2];
        float4 b = reinterpret_cast<const float4*>(E)[k * 2 + 1];
        __nv_bfloat162 p0 = __floats2bfloat162_rn(a.x, a.y);
        __nv_bfloat162 p1 = __floats2bfloat162_rn(a.z, a.w);
        __nv_bfloat162 p2 = __floats2bfloat162_rn(b.x, b.y);
        __nv_bfloat162 p3 = __floats2bfloat162_rn(b.z, b.w);
        uint4 o;
        o.x = *reinterpret_cast<uint32_t*>(&p0);
        o.y = *reinterpret_cast<uint32_t*>(&p1);
        o.z = *reinterpret_cast<uint32_t*>(&p2);
        o.w = *reinterpret_cast<uint32_t*>(&p3);
        reinterpret_cast<uint4*>(g_Eh)[k] = o;
    }
}

// ---------------------------------------------------------------------------
// helpers
// ---------------------------------------------------------------------------
__device__ __forceinline__ void mma16816(float* d, const uint32_t* a,
                                         uint32_t b0, uint32_t b1)
{
    asm volatile(
        "mma.sync.aligned.m16n8k16.row.col.f32.bf16.bf16.f32 "
        "{%0,%1,%2,%3}, {%4,%5,%6,%7}, {%8,%9}, {%0,%1,%2,%3};\n"
        : "+f"(d[0]), "+f"(d[1]), "+f"(d[2]), "+f"(d[3])
        : "r"(a[0]), "r"(a[1]), "r"(a[2]), "r"(a[3]), "r"(b0), "r"(b1));
}
__device__ __forceinline__ void ldsm_x4(uint32_t* r, uint32_t addr)
{
    asm volatile("ldmatrix.sync.aligned.m8n8.x4.shared.b16 {%0,%1,%2,%3}, [%4];\n"
                 : "=r"(r[0]), "=r"(r[1]), "=r"(r[2]), "=r"(r[3]) : "r"(addr));
}
__device__ __forceinline__ void ldsm_x4_t(uint32_t* r, uint32_t addr)
{
    asm volatile("ldmatrix.sync.aligned.m8n8.x4.trans.shared.b16 {%0,%1,%2,%3}, [%4];\n"
                 : "=r"(r[0]), "=r"(r[1]), "=r"(r[2]), "=r"(r[3]) : "r"(addr));
}
__device__ __forceinline__ void cp16(uint32_t saddr, const void* gaddr)
{
    asm volatile("cp.async.cg.shared.global [%0], [%1], 16;\n"
                 :: "r"(saddr), "l"(gaddr) : "memory");
}

// ---------------------------------------------------------------------------
// Kernel A: tensor-core GEMM  U = Eh @ Wh + E + hb
// Round-3 tiling (BM=BN=BK=64, 256 thr, warp tile 32x16) with a SIX-stage
// cp.async ring (wait_group 4): ~4-5 iterations of lookahead (>600 cyc)
// hides DRAM/L2 latency that the 2-stage version exposed every iteration.
// Stage it+5 writes buffer (it-1)%6; the per-iter barrier guarantees all
// warps finished mma(it-1) first -> race-free with ONE barrier per iter.
// smem: 6 x (8K A + 8K B) = 96 KB dynamic.
// ---------------------------------------------------------------------------
__global__ __launch_bounds__(256) void gemm_u_kernel(
    const float* __restrict__ E, const float* __restrict__ hb)
{
    extern __shared__ __align__(1024) char smem[];
    const uint32_t base = (uint32_t)__cvta_generic_to_shared(smem);
    // sA(s) = base + s*8192 ; sB(s) = base + 49152 + s*8192   (s = 0..5)

    const int tid  = threadIdx.x;
    const int lane = tid & 31;
    const int wid  = tid >> 5;
    const int wm   = (wid >> 2) << 5;   // 0 / 32
    const int wn   = (wid & 3) << 4;    // 0,16,32,48
    const int bm   = blockIdx.y << 6;
    const int bn   = blockIdx.x << 6;

    float acc[2][2][4];
    #pragma unroll
    for (int i = 0; i < 2; i++)
        #pragma unroll
        for (int j = 0; j < 2; j++)
            #pragma unroll
            for (int k = 0; k < 4; k++) acc[i][j][k] = 0.f;

    const int r0 = tid >> 3;
    const int c0 = tid & 7;
    const uint32_t swzOff  = (uint32_t)((r0 << 7) + ((c0 ^ (r0 & 7)) << 4));
    const uint32_t swzOff2 = swzOff + (32 << 7);

    const __nv_bfloat16* gA  = g_Eh + (size_t)(bm + r0) * DD + c0 * 8;
    const __nv_bfloat16* gA2 = gA + (size_t)32 * DD;
    const __nv_bfloat16* gB  = g_Wh + (size_t)r0 * DD + bn + c0 * 8;
    const __nv_bfloat16* gB2 = gB + (size_t)32 * DD;

    const int l15 = lane & 15;
    const int l7  = lane & 7;
    const int kcB = lane >> 4;
    uint32_t aRow[2];
    #pragma unroll
    for (int im = 0; im < 2; im++) aRow[im] = (uint32_t)((wm + im * 16 + l15) << 7);
    const int nChunkBase = wn >> 3;

    #define LOAD_TILES(stg, k0)                                            \
        {                                                                  \
            const uint32_t sa = base + (uint32_t)((stg) * 8192);           \
            const uint32_t sb = base + 49152u + (uint32_t)((stg) * 8192);  \
            cp16(sa + swzOff,  gA  + (k0));                                \
            cp16(sa + swzOff2, gA2 + (k0));                                \
            cp16(sb + swzOff,  gB  + (size_t)(k0) * DD);                   \
            cp16(sb + swzOff2, gB2 + (size_t)(k0) * DD);                   \
            asm volatile("cp.async.commit_group;\n" ::: "memory");         \
        }

    // prologue: stages 0..4 in flight
    #pragma unroll
    for (int p = 0; p < 5; p++) LOAD_TILES(p, p * 64);

    const int NIT = DD / 64;   // 32
    for (int it = 0; it < NIT; it++) {
        if (it + 4 < NIT)
            asm volatile("cp.async.wait_group 4;\n" ::: "memory");
        else
            asm volatile("cp.async.wait_group 0;\n" ::: "memory");
        __syncthreads();

        if (it + 5 < NIT) LOAD_TILES((it + 5) % 6, (it + 5) * 64);

        const int s = it % 6;
        const uint32_t sa = base + (uint32_t)(s * 8192);
        const uint32_t sb = base + 49152u + (uint32_t)(s * 8192);
        #pragma unroll
        for (int kk = 0; kk < 4; kk++) {
            uint32_t a[2][4], b[4];
            const int kchunk = kk * 2 + kcB;
            #pragma unroll
            for (int im = 0; im < 2; im++)
                ldsm_x4(a[im], sa + aRow[im] + (uint32_t)((kchunk ^ l7) << 4));
            {
                const int krow = kk * 16 + l15;
                const int nchunk = nChunkBase + kcB;
                ldsm_x4_t(b, sb + (uint32_t)(krow << 7)
                               + (uint32_t)((nchunk ^ (krow & 7)) << 4));
            }
            #pragma unroll
            for (int im = 0; im < 2; im++) {
                mma16816(acc[im][0], a[im], b[0], b[1]);
                mma16816(acc[im][1], a[im], b[2], b[3]);
            }
        }
        // no trailing barrier: next iter's barrier precedes any reuse of
        // buffer (it)%6 (reused only at issue of stage it+6, i.e. iter it+1).
    }
    #undef LOAD_TILES

    // epilogue: u = acc + E (exact identity) + hb
    #pragma unroll
    for (int im = 0; im < 2; im++) {
        const int row0e = bm + wm + im * 16 + (lane >> 2);
        #pragma unroll
        for (int in = 0; in < 2; in++) {
            const int col = bn + wn + in * 8 + ((lane & 3) << 1);
            const float h0 = hb[col], h1 = hb[col + 1];
            g_u[(size_t)row0e * DD + col]
                = acc[im][in][0] + E[(size_t)row0e * DD + col] + h0;
            g_u[(size_t)row0e * DD + col + 1]
                = acc[im][in][1] + E[(size_t)row0e * DD + col + 1] + h1;
            g_u[(size_t)(row0e + 8) * DD + col]
                = acc[im][in][2] + E[(size_t)(row0e + 8) * DD + col] + h0;
            g_u[(size_t)(row0e + 8) * DD + col + 1]
                = acc[im][in][3] + E[(size_t)(row0e + 8) * DD + col + 1] + h1;
        }
    }
}

// ---------------------------------------------------------------------------
// Kernel B: scoring (round-8 passing version, verbatim). Single wave:
// grid (256, 8) x 128 thr, 16 CTAs/SM.
// ---------------------------------------------------------------------------
__global__ __launch_bounds__(128, 16) void score_kernel(
    const float* __restrict__ E,
    const float* __restrict__ theo,
    const float* __restrict__ cand,
    const float* __restrict__ vb,
    float* __restrict__ out)
{
    const int b    = blockIdx.x;
    const int tc   = blockIdx.y;       // 0..7
    const int tid  = threadIdx.x;
    const int lane = tid & 31;
    const int wid  = tid >> 5;         // 0..3

    __shared__ float u_s[DD];
    __shared__ float red[8];
    __shared__ float s_vb, s_pos;

    float pv = 0.f, pp = 0.f;
    #pragma unroll
    for (int h = 0; h < 4; h++) {
        const int i = h * 512 + tid * 4;
        float4 u4 = *reinterpret_cast<const float4*>(&g_u[(size_t)b * DD + i]);
        *reinterpret_cast<float4*>(&u_s[i]) = u4;
        float4 e4 = *reinterpret_cast<const float4*>(&E[(size_t)b * DD + i]);
        float4 v4 = *reinterpret_cast<const float4*>(&vb[i]);
        pv += e4.x * v4.x + e4.y * v4.y + e4.z * v4.z + e4.w * v4.w;
        if (tc == 0) {
            float4 c4 = *reinterpret_cast<const float4*>(&cand[(size_t)b * DD + i]);
            pp += u4.x * c4.x + u4.y * c4.y + u4.z * c4.z + u4.w * c4.w;
        }
    }
    #pragma unroll
    for (int o = 16; o > 0; o >>= 1) {
        pv += __shfl_xor_sync(0xFFFFFFFFu, pv, o);
        pp += __shfl_xor_sync(0xFFFFFFFFu, pp, o);
    }
    if (lane == 0) { red[wid] = pv; red[4 + wid] = pp; }
    __syncthreads();
    if (tid == 0) {
        float v = red[0] + red[1] + red[2] + red[3];
        float p = red[4] + red[5] + red[6] + red[7];
        s_vb  = v;
        s_pos = p + v;
    }
    __syncthreads();
    const float vbb = s_vb;

    const int t0 = tc * 8 + wid * 2;
    const float4* ra  = reinterpret_cast<const float4*>(&theo[((size_t)b * TT + t0) * DD]);
    const float4* rb  = ra + DD / 4;
    const float4* u4p = reinterpret_cast<const float4*>(u_s);

    float s0 = 0.f, s1 = 0.f;
    #pragma unroll 4
    for (int i = lane; i < DD / 4; i += 32) {
        float4 x = __ldcs(&ra[i]);
        float4 y = __ldcs(&rb[i]);
        float4 u = u4p[i];
        s0 += x.x * u.x + x.y * u.y + x.z * u.z + x.w * u.w;
        s1 += y.x * u.x + y.y * u.y + y.z * u.z + y.w * u.w;
    }
    #pragma unroll
    for (int o = 16; o > 0; o >>= 1) {
        s0 += __shfl_xor_sync(0xFFFFFFFFu, s0, o);
        s1 += __shfl_xor_sync(0xFFFFFFFFu, s1, o);
    }
    if (lane == 0) {
        out[b * (TT + 1) + 1 + t0]     = s0 + vbb;
        out[b * (TT + 1) + 1 + t0 + 1] = s1 + vbb;
    }
    if (tc == 0 && tid == 0) out[b * (TT + 1)] = s_pos;
}

// ---------------------------------------------------------------------------
// launch: 0=experimental [B,D], 1=theoretical [B,T,D], 2=candidate [B,D],
//         3=W [D,D], 4=vb [D], 5=hb [D] ; out fp32 [B, 1+T]
// ---------------------------------------------------------------------------
extern "C" void kernel_launch(void* const* d_in, const int* in_sizes, int n_in,
                              void* d_out, int out_size)
{
    const float* E    = (const float*)d_in[0];
    const float* theo = (const float*)d_in[1];
    const float* cand = (const float*)d_in[2];
    const float* W    = (const float*)d_in[3];
    const float* vb   = (const float*)d_in[4];
    const float* hb   = (const float*)d_in[5];
    float*       out  = (float*)d_out;

    const int SMEM = 12 * 8192;   // 96 KB dynamic
    cudaFuncSetAttribute(gemm_u_kernel,
                         cudaFuncAttributeMaxDynamicSharedMemorySize, SMEM);

    const int npairs = DD * DD / 8 + BB * DD / 8;   // 589824
    convert_kernel<<<npairs / 256, 256>>>(E, W);
    gemm_u_kernel<<<dim3(DD / 64, BB / 64), 256, SMEM>>>(E, hb);
    score_kernel<<<dim3(BB, 8), 128>>>(E, theo, cand, vb, out);
}